// round 5
// baseline (speedup 1.0000x reference)
#include <cuda_runtime.h>

// LSTMPredictor: B=1024, T=512, I=4, H=128 (4H=512 gates), O=4.
// Persistent-CTA fp32 LSTM, packed fma.rn.f32x2 (FFMA2) inner product.
// 128 CTAs x 256 threads; CTA owns 8 batch rows for all 512 steps.
// K extended to 134: rows [0:128)=h, [128:132)=x_t, 132=1 (bias), 133=0 (pad).

#define B_SZ    1024
#define T_SZ    512
#define H_SZ    128
#define G_SZ    512            // 4*H
#define K_EXT   134
#define KH      67             // K per k-half
#define NB      8
#define CTAS    (B_SZ / NB)    // 128
#define THREADS 256

typedef unsigned long long ull;

// ---------------- device scratch (allocation-free) ----------------
__device__ __align__(16) float g_Wt[K_EXT * G_SZ];  // Wt[k][g]

__global__ void prep_kernel(const float* __restrict__ W_hh,
                            const float* __restrict__ W_ih,
                            const float* __restrict__ b_ih,
                            const float* __restrict__ b_hh)
{
    int idx = blockIdx.x * blockDim.x + threadIdx.x;
    if (idx >= K_EXT * G_SZ) return;
    int k = idx / G_SZ;
    int g = idx - k * G_SZ;
    float v;
    if (k < H_SZ)           v = W_hh[g * H_SZ + k];
    else if (k < H_SZ + 4)  v = W_ih[g * 4 + (k - H_SZ)];
    else if (k == 132)      v = b_ih[g] + b_hh[g];
    else                    v = 0.0f;
    g_Wt[idx] = v;
}

// ---------------- packed-f32x2 helpers ----------------
__device__ __forceinline__ ull pack2(float v) {
    ull r;
    asm("mov.b64 %0, {%1, %1};" : "=l"(r) : "f"(v));
    return r;
}
__device__ __forceinline__ void fma2(ull& d, ull a, ull b) {
    asm("fma.rn.f32x2 %0, %1, %2, %0;" : "+l"(d) : "l"(a), "l"(b));
}
__device__ __forceinline__ float2 unpack2(ull v) {
    float2 r;
    asm("mov.b64 {%0, %1}, %2;" : "=f"(r.x), "=f"(r.y) : "l"(v));
    return r;
}

// ---------------- activations (overflow-safe, MUFU-based) ----------------
__device__ __forceinline__ float sigf(float x) {
    return __fdividef(1.0f, 1.0f + __expf(-x));
}
__device__ __forceinline__ float tanhf_fast(float x) {
    return 1.0f - __fdividef(2.0f, __expf(2.0f * x) + 1.0f);
}

// smem layout (floats):
//   part [2][NB][512] : 8192   @ 0      k-split partial gate sums
//   h_buf[134][NB]    : 1072   @ 8192   extended state [h; x; 1; 0], k-major
#define SM_PART  0
#define SM_H     8192
#define SM_TOTAL 9280          // 37120 bytes (pad a little)

__global__ __launch_bounds__(THREADS)
void lstm_kernel(const float* __restrict__ x,
                 const float* __restrict__ W_fc,
                 const float* __restrict__ b_fc,
                 float* __restrict__ out)
{
    __shared__ __align__(16) float sm[SM_TOTAL];
    float* part  = sm + SM_PART;
    float* h_buf = sm + SM_H;

    const int t  = threadIdx.x;
    const int ks = t >> 7;        // k-half 0/1 (67 k each)
    const int gt = t & 127;       // gate-quad: gates [4*gt, 4*gt+4)
    const int bb = blockIdx.x * NB;

    const int j    = t & 127;     // epilogue: hidden unit
    const int half = t >> 7;      // epilogue: batch half

    // ---- init extended state: h=0, x slot filled below, ones row, zero row
    for (int i = t; i < K_EXT * NB; i += THREADS) {
        int k = i >> 3;
        h_buf[i] = (k == 132) ? 1.0f : 0.0f;
    }
    __syncthreads();
    const float4* x4 = reinterpret_cast<const float4*>(x);
    if (t < NB) {
        float4 xv = x4[(bb + t) * T_SZ + 0];
        h_buf[128 * NB + t] = xv.x;
        h_buf[129 * NB + t] = xv.y;
        h_buf[130 * NB + t] = xv.z;
        h_buf[131 * NB + t] = xv.w;
    }
    __syncthreads();

    float creg[4] = {0.0f, 0.0f, 0.0f, 0.0f};

    const float4* Wt4 = reinterpret_cast<const float4*>(g_Wt);
    float4* part4     = reinterpret_cast<float4*>(part);

    const int kbase = ks * KH;

    for (int step = 0; step < T_SZ; ++step) {
        // prefetch next step's x into registers (latency hidden under GEMM)
        float4 xnext;
        const bool xldr = (t < NB) && (step + 1 < T_SZ);
        if (xldr) xnext = x4[(bb + t) * T_SZ + step + 1];

        // ---- recurrent GEMM: f32x2 accumulators [batch-pair][gate] ----
        ull acc[4][4];
#pragma unroll
        for (int bp = 0; bp < 4; ++bp)
#pragma unroll
            for (int gi = 0; gi < 4; ++gi) acc[bp][gi] = 0ull;

#pragma unroll 4
        for (int kk = 0; kk < KH; ++kk) {
            const int k = kbase + kk;
            const float4 w = Wt4[k * (G_SZ / 4) + gt];      // coalesced LDG.128
            ull wp[4];
            wp[0] = pack2(w.x); wp[1] = pack2(w.y);
            wp[2] = pack2(w.z); wp[3] = pack2(w.w);
            const ull* hp = reinterpret_cast<const ull*>(h_buf + k * NB);
            ull h0 = hp[0], h1 = hp[1], h2 = hp[2], h3 = hp[3]; // LDS.64 bcast
#pragma unroll
            for (int gi = 0; gi < 4; ++gi) {
                fma2(acc[0][gi], h0, wp[gi]);
                fma2(acc[1][gi], h1, wp[gi]);
                fma2(acc[2][gi], h2, wp[gi]);
                fma2(acc[3][gi], h3, wp[gi]);
            }
        }

        // ---- store partials: part[ks][b][g], conflict-free STS.128 ----
#pragma unroll
        for (int bp = 0; bp < 4; ++bp) {
            float2 a0 = unpack2(acc[bp][0]);
            float2 a1 = unpack2(acc[bp][1]);
            float2 a2 = unpack2(acc[bp][2]);
            float2 a3 = unpack2(acc[bp][3]);
            part4[((ks * NB + 2 * bp) * G_SZ) / 4 + gt] =
                make_float4(a0.x, a1.x, a2.x, a3.x);
            part4[((ks * NB + 2 * bp + 1) * G_SZ) / 4 + gt] =
                make_float4(a0.y, a1.y, a2.y, a3.y);
        }
        __syncthreads();

        // ---- epilogue: thread owns hidden j for 4 batch rows ----
#pragma unroll
        for (int bi = 0; bi < 4; ++bi) {
            const int b = half * 4 + bi;
            float pre[4];
#pragma unroll
            for (int q = 0; q < 4; ++q) {
                const int g = q * H_SZ + j;
                pre[q] = part[b * G_SZ + g] + part[(NB + b) * G_SZ + g];
            }
            const float ig = sigf(pre[0]);
            const float fg = sigf(pre[1]);
            const float gg = tanhf_fast(pre[2]);
            const float og = sigf(pre[3]);
            float c = fg * creg[bi] + ig * gg;
            creg[bi] = c;
            h_buf[j * NB + b] = og * tanhf_fast(c);
        }
        // stage next x into extended-state rows
        if (xldr) {
            h_buf[128 * NB + t] = xnext.x;
            h_buf[129 * NB + t] = xnext.y;
            h_buf[130 * NB + t] = xnext.z;
            h_buf[131 * NB + t] = xnext.w;
        }
        __syncthreads();
    }

    // ---- final FC: out[b][o] = h_T[b] . W_fc[o] + b_fc[o] ----
    if (t < NB * 4) {
        const int b = t >> 2;
        const int o = t & 3;
        float s = b_fc[o];
#pragma unroll 8
        for (int jj = 0; jj < H_SZ; ++jj)
            s += h_buf[jj * NB + b] * W_fc[o * H_SZ + jj];
        out[(bb + b) * 4 + o] = s;
    }
}

// ---------------- launch ----------------
extern "C" void kernel_launch(void* const* d_in, const int* in_sizes, int n_in,
                              void* d_out, int out_size)
{
    const float* x    = (const float*)d_in[0];
    const float* W_ih = (const float*)d_in[1];
    const float* W_hh = (const float*)d_in[2];
    const float* b_ih = (const float*)d_in[3];
    const float* b_hh = (const float*)d_in[4];
    const float* W_fc = (const float*)d_in[5];
    const float* b_fc = (const float*)d_in[6];
    float* out = (float*)d_out;

    prep_kernel<<<(K_EXT * G_SZ + 255) / 256, 256>>>(W_hh, W_ih, b_ih, b_hh);
    lstm_kernel<<<CTAS, THREADS>>>(x, W_fc, b_fc, out);
}